// round 7
// baseline (speedup 1.0000x reference)
#include <cuda_runtime.h>
#include <cuda_bf16.h>

#define Bn 8
#define Sn 2048
#define Dn 256
#define Hn 4
#define DHn 64

// ---------------- scratch (static device arrays; no allocation) ----------------
__device__ __nv_bfloat16 g_qh[Bn*Hn*Sn*DHn];  // 8 MB each: pre-split Q/K (hi/lo bf16)
__device__ __nv_bfloat16 g_ql[Bn*Hn*Sn*DHn];
__device__ __nv_bfloat16 g_kh[Bn*Hn*Sn*DHn];
__device__ __nv_bfloat16 g_kl[Bn*Hn*Sn*DHn];
__device__ float g_vs[Bn*Sn*DHn];             // 4 MB  [B,S,DH], tf32-pre-rounded
__device__ float g_heads[Bn*Hn*Sn*DHn];       // 16 MB [B,H,S,DH] (carries 1/(4*rowsum))
__device__ float g_rowsum[Bn*Hn*Sn];          // 256 KB
__device__ unsigned g_mbits[Bn*Sn*(Sn/32)];   // 16.8 MB bit-packed mask

// ---------------- helpers ----------------
__device__ __forceinline__ unsigned f2tf(float x) {
    unsigned u;
    asm("cvt.rna.tf32.f32 %0, %1;" : "=r"(u) : "f"(x));
    return u;
}
__device__ __forceinline__ float tf32r(float x) { return __uint_as_float(f2tf(x)); }
__device__ __forceinline__ void mma8(float* c, const unsigned* a, const unsigned* b) {
    asm volatile("mma.sync.aligned.m16n8k8.row.col.f32.tf32.tf32.f32 "
        "{%0,%1,%2,%3}, {%4,%5,%6,%7}, {%8,%9}, {%0,%1,%2,%3};\n"
        : "+f"(c[0]), "+f"(c[1]), "+f"(c[2]), "+f"(c[3])
        : "r"(a[0]), "r"(a[1]), "r"(a[2]), "r"(a[3]), "r"(b[0]), "r"(b[1]));
}
__device__ __forceinline__ void mma16(float* c, const unsigned* a, const unsigned* b) {
    asm volatile("mma.sync.aligned.m16n8k16.row.col.f32.bf16.bf16.f32 "
        "{%0,%1,%2,%3}, {%4,%5,%6,%7}, {%8,%9}, {%0,%1,%2,%3};\n"
        : "+f"(c[0]), "+f"(c[1]), "+f"(c[2]), "+f"(c[3])
        : "r"(a[0]), "r"(a[1]), "r"(a[2]), "r"(a[3]), "r"(b[0]), "r"(b[1]));
}
__device__ __forceinline__ void bsplit(float x, __nv_bfloat16 &hi, __nv_bfloat16 &lo) {
    hi = __float2bfloat16_rn(x);
    lo = __float2bfloat16_rn(x - __bfloat162float(hi));
}

// FMA-pipe exp(s/8): magic-constant round + degree-5 poly + exponent splice. rel err ~2e-6.
__device__ __forceinline__ float fexp8(float s) {
    const float c = 0.18033688011112042f;   // log2(e)/8
    const float MAGIC = 12582912.0f;        // 1.5 * 2^23
    float t = fmaf(s, c, MAGIC);
    float k = t - MAGIC;
    float f = fmaf(s, c, -k);               // f in [-0.5, 0.5]
    float p = 1.3333558146e-3f;
    p = fmaf(p, f, 9.6181291076e-3f);
    p = fmaf(p, f, 5.5504108665e-2f);
    p = fmaf(p, f, 2.4022650696e-1f);
    p = fmaf(p, f, 6.9314718056e-1f);
    p = fmaf(p, f, 1.0f);
    int ik = __float_as_int(t) << 23;
    return __int_as_float(__float_as_int(p) + ik);
}

// ================= Kernel 1: projections + fused mask pack =================
// blocks [0, 1536): proj. z = bx/512: 0 -> qs (bf16 hi/lo), 1 -> ks, 2 -> vs (tf32)
// blocks [1536, 1536+131072): bit-pack mask (overlaps DRAM read with proj tensor work)
#define PROJ_BLOCKS 1536
#define PACK_BLOCKS ((Bn * Sn * Sn) / 256)
__global__ __launch_bounds__(256) void proj_pack_kernel(
    const float* __restrict__ q, const float* __restrict__ k, const float* __restrict__ v,
    const float* __restrict__ Wq, const float* __restrict__ Wk, const float* __restrict__ Wv,
    const int* __restrict__ mask)
{
    if (blockIdx.x >= PROJ_BLOCKS) {
        size_t i = (size_t)(blockIdx.x - PROJ_BLOCKS) * 256 + threadIdx.x;
        int m = mask[i] != 0;
        unsigned bal = __ballot_sync(0xffffffffu, m);
        if ((threadIdx.x & 31) == 0) g_mbits[i >> 5] = bal;
        return;
    }
    int z = blockIdx.x >> 9;           // /512
    int rem = blockIdx.x & 511;
    int hx = rem & 3;
    int My = rem >> 2;
    if (z == 2 && hx > 0) return;

    __shared__ __nv_bfloat16 Ah[128][40];
    __shared__ __nv_bfloat16 Al[128][40];
    __shared__ __nv_bfloat16 Bh[64][40];   // stored as [n][k]
    __shared__ __nv_bfloat16 Bl[64][40];

    const float* X = (z == 0) ? q : (z == 1) ? k : v;
    const float* W = (z == 0) ? (Wq + (size_t)hx * Dn * DHn)
                   : (z == 1) ? (Wk + (size_t)hx * Dn * DHn) : Wv;
    int M0 = My * 128;
    int tid = threadIdx.x;
    int warp = tid >> 5, lane = tid & 31;
    int g = lane >> 2, t = lane & 3;
    int wm0 = (warp >> 1) * 32, wn0 = (warp & 1) * 32;

    float c[2][4][4];
    #pragma unroll
    for (int mt = 0; mt < 2; mt++)
        #pragma unroll
        for (int nt = 0; nt < 4; nt++)
            #pragma unroll
            for (int i = 0; i < 4; i++) c[mt][nt][i] = 0.f;

    for (int kc = 0; kc < 8; kc++) {
        int K0 = kc * 32;
        #pragma unroll
        for (int it = 0; it < 4; it++) {
            int i = tid + it * 256;
            int r = i >> 3, c4 = (i & 7) << 2;
            float4 val = *reinterpret_cast<const float4*>(&X[(size_t)(M0 + r) * Dn + K0 + c4]);
            __nv_bfloat16 hi, lo;
            bsplit(val.x, hi, lo); Ah[r][c4]   = hi; Al[r][c4]   = lo;
            bsplit(val.y, hi, lo); Ah[r][c4+1] = hi; Al[r][c4+1] = lo;
            bsplit(val.z, hi, lo); Ah[r][c4+2] = hi; Al[r][c4+2] = lo;
            bsplit(val.w, hi, lo); Ah[r][c4+3] = hi; Al[r][c4+3] = lo;
        }
        #pragma unroll
        for (int it = 0; it < 2; it++) {
            int i = tid + it * 256;
            int r = i >> 4, c4 = (i & 15) << 2;   // r = k row (0..31), c4 = n
            float4 val = *reinterpret_cast<const float4*>(&W[(size_t)(K0 + r) * DHn + c4]);
            __nv_bfloat16 hi, lo;
            bsplit(val.x, hi, lo); Bh[c4][r]   = hi; Bl[c4][r]   = lo;
            bsplit(val.y, hi, lo); Bh[c4+1][r] = hi; Bl[c4+1][r] = lo;
            bsplit(val.z, hi, lo); Bh[c4+2][r] = hi; Bl[c4+2][r] = lo;
            bsplit(val.w, hi, lo); Bh[c4+3][r] = hi; Bl[c4+3][r] = lo;
        }
        __syncthreads();
        #pragma unroll
        for (int kk = 0; kk < 2; kk++) {
            int k0 = kk * 16;
            unsigned ah[2][4], al[2][4], bh[4][2], bl[4][2];
            #pragma unroll
            for (int mt = 0; mt < 2; mt++) {
                int rb = wm0 + mt * 16;
                ah[mt][0] = *reinterpret_cast<const unsigned*>(&Ah[rb + g][k0 + 2*t]);
                ah[mt][1] = *reinterpret_cast<const unsigned*>(&Ah[rb + 8 + g][k0 + 2*t]);
                ah[mt][2] = *reinterpret_cast<const unsigned*>(&Ah[rb + g][k0 + 8 + 2*t]);
                ah[mt][3] = *reinterpret_cast<const unsigned*>(&Ah[rb + 8 + g][k0 + 8 + 2*t]);
                al[mt][0] = *reinterpret_cast<const unsigned*>(&Al[rb + g][k0 + 2*t]);
                al[mt][1] = *reinterpret_cast<const unsigned*>(&Al[rb + 8 + g][k0 + 2*t]);
                al[mt][2] = *reinterpret_cast<const unsigned*>(&Al[rb + g][k0 + 8 + 2*t]);
                al[mt][3] = *reinterpret_cast<const unsigned*>(&Al[rb + 8 + g][k0 + 8 + 2*t]);
            }
            #pragma unroll
            for (int nt = 0; nt < 4; nt++) {
                int cb = wn0 + nt * 8 + g;
                bh[nt][0] = *reinterpret_cast<const unsigned*>(&Bh[cb][k0 + 2*t]);
                bh[nt][1] = *reinterpret_cast<const unsigned*>(&Bh[cb][k0 + 8 + 2*t]);
                bl[nt][0] = *reinterpret_cast<const unsigned*>(&Bl[cb][k0 + 2*t]);
                bl[nt][1] = *reinterpret_cast<const unsigned*>(&Bl[cb][k0 + 8 + 2*t]);
            }
            #pragma unroll
            for (int mt = 0; mt < 2; mt++)
                #pragma unroll
                for (int nt = 0; nt < 4; nt++) {
                    mma16(c[mt][nt], ah[mt], bh[nt]);
                    mma16(c[mt][nt], ah[mt], bl[nt]);
                    mma16(c[mt][nt], al[mt], bh[nt]);
                }
        }
        __syncthreads();
    }
    #pragma unroll
    for (int mt = 0; mt < 2; mt++)
        #pragma unroll
        for (int nt = 0; nt < 4; nt++) {
            int e = wn0 + nt * 8 + 2 * t;
            #pragma unroll
            for (int half = 0; half < 2; half++) {
                int r = M0 + wm0 + mt * 16 + half * 8 + g;
                int bb = r >> 11, s = r & 2047;
                float v0 = c[mt][nt][half * 2], v1 = c[mt][nt][half * 2 + 1];
                if (z == 2) {
                    *reinterpret_cast<float2*>(&g_vs[((size_t)bb * Sn + s) * DHn + e]) =
                        make_float2(tf32r(v0), tf32r(v1));
                } else {
                    size_t idx = (((size_t)(bb * Hn + hx)) * Sn + s) * DHn + e;
                    __nv_bfloat16 h0, l0, h1, l1;
                    bsplit(v0, h0, l0); bsplit(v1, h1, l1);
                    __nv_bfloat162 vh; vh.x = h0; vh.y = h1;
                    __nv_bfloat162 vl; vl.x = l0; vl.y = l1;
                    if (z == 0) {
                        *reinterpret_cast<__nv_bfloat162*>(&g_qh[idx]) = vh;
                        *reinterpret_cast<__nv_bfloat162*>(&g_ql[idx]) = vl;
                    } else {
                        *reinterpret_cast<__nv_bfloat162*>(&g_kh[idx]) = vh;
                        *reinterpret_cast<__nv_bfloat162*>(&g_kl[idx]) = vl;
                    }
                }
            }
        }
}

// ================= Kernel 2: fused attention =================
__global__ __launch_bounds__(256) void attn_kernel(float* __restrict__ attn_out)
{
    extern __shared__ char smraw[];
    __nv_bfloat16 (*Qh)[72] = reinterpret_cast<__nv_bfloat16(*)[72]>(smraw);            // 128x72
    __nv_bfloat16 (*Ql)[72] = reinterpret_cast<__nv_bfloat16(*)[72]>(smraw + 18432);
    __nv_bfloat16 (*Kh)[72] = reinterpret_cast<__nv_bfloat16(*)[72]>(smraw + 36864);    // 64x72
    __nv_bfloat16 (*Kl)[72] = reinterpret_cast<__nv_bfloat16(*)[72]>(smraw + 46080);
    float (*Vs)[72] = reinterpret_cast<float(*)[72]>(smraw + 55296);                    // 64x72 f32
    float (*Ps)[68] = reinterpret_cast<float(*)[68]>(smraw + 73728);                    // 128x68 f32
    unsigned (*m2)[2] = reinterpret_cast<unsigned(*)[2]>(smraw + 108544);               // 128x2
    float* rowsum = reinterpret_cast<float*>(smraw + 109568);                           // 128

    int st = blockIdx.x, h = blockIdx.y, b = blockIdx.z;
    int bh = b * Hn + h;
    int S0 = st * 128;
    int tid = threadIdx.x, warp = tid >> 5, lane = tid & 31;
    int g = lane >> 2, t = lane & 3;
    int wm0 = (warp >> 1) * 32, wn0 = (warp & 1) * 32;

    const __nv_bfloat16* qh_src = g_qh + ((size_t)bh * Sn + S0) * DHn;
    const __nv_bfloat16* ql_src = g_ql + ((size_t)bh * Sn + S0) * DHn;
    const __nv_bfloat16* kh_src = g_kh + (size_t)bh * Sn * DHn;
    const __nv_bfloat16* kl_src = g_kl + (size_t)bh * Sn * DHn;
    const float* vsrc = g_vs + (size_t)b * Sn * DHn;
    const unsigned* msrc = g_mbits + ((size_t)b * Sn + S0) * (Sn / 32);
    float* aout = attn_out + (size_t)bh * Sn * Sn;

    // stage Q hi/lo (pure copies, no cvt)
    #pragma unroll
    for (int it = 0; it < 4; it++) {
        int i = tid + it * 256;
        int r = i >> 3, c8 = (i & 7) << 3;
        *reinterpret_cast<uint4*>(&Qh[r][c8]) =
            *reinterpret_cast<const uint4*>(&qh_src[(size_t)r * DHn + c8]);
        *reinterpret_cast<uint4*>(&Ql[r][c8]) =
            *reinterpret_cast<const uint4*>(&ql_src[(size_t)r * DHn + c8]);
    }
    if (tid < 128) rowsum[tid] = 0.f;

    float cO[2][4][4];
    #pragma unroll
    for (int mt = 0; mt < 2; mt++)
        #pragma unroll
        for (int nt = 0; nt < 4; nt++)
            #pragma unroll
            for (int i = 0; i < 4; i++) cO[mt][nt][i] = 0.f;
    float rpart[2][2] = {{0.f, 0.f}, {0.f, 0.f}};

    for (int tc = 0; tc < 32; tc++) {
        int T0 = tc * 64;
        // stage K hi/lo (copies) + V (pre-rounded f32) + mask words
        #pragma unroll
        for (int it = 0; it < 2; it++) {
            int i = tid + it * 256;
            int r = i >> 3, c8 = (i & 7) << 3;
            *reinterpret_cast<uint4*>(&Kh[r][c8]) =
                *reinterpret_cast<const uint4*>(&kh_src[(size_t)(T0 + r) * DHn + c8]);
            *reinterpret_cast<uint4*>(&Kl[r][c8]) =
                *reinterpret_cast<const uint4*>(&kl_src[(size_t)(T0 + r) * DHn + c8]);
        }
        #pragma unroll
        for (int it = 0; it < 4; it++) {
            int i = tid + it * 256;
            int r = i >> 4, c4 = (i & 15) << 2;
            float4 vv = *reinterpret_cast<const float4*>(&vsrc[(size_t)(T0 + r) * DHn + c4]);
            Vs[r][c4] = vv.x; Vs[r][c4+1] = vv.y; Vs[r][c4+2] = vv.z; Vs[r][c4+3] = vv.w;
        }
        { // 128 rows x 2 mask words
            int r = tid >> 1, w = tid & 1;
            m2[r][w] = msrc[(size_t)r * (Sn / 32) + (T0 >> 5) + w];
        }
        __syncthreads();

        // ---- QK^T (bf16x3) ----
        float cS[2][4][4];
        #pragma unroll
        for (int mt = 0; mt < 2; mt++)
            #pragma unroll
            for (int nt = 0; nt < 4; nt++)
                #pragma unroll
                for (int i = 0; i < 4; i++) cS[mt][nt][i] = 0.f;
        #pragma unroll
        for (int kk = 0; kk < 4; kk++) {
            int k0 = kk * 16;
            unsigned ah[2][4], al[2][4], bhf[4][2], blf[4][2];
            #pragma unroll
            for (int mt = 0; mt < 2; mt++) {
                int rb = wm0 + mt * 16;
                ah[mt][0] = *reinterpret_cast<const unsigned*>(&Qh[rb + g][k0 + 2*t]);
                ah[mt][1] = *reinterpret_cast<const unsigned*>(&Qh[rb + 8 + g][k0 + 2*t]);
                ah[mt][2] = *reinterpret_cast<const unsigned*>(&Qh[rb + g][k0 + 8 + 2*t]);
                ah[mt][3] = *reinterpret_cast<const unsigned*>(&Qh[rb + 8 + g][k0 + 8 + 2*t]);
                al[mt][0] = *reinterpret_cast<const unsigned*>(&Ql[rb + g][k0 + 2*t]);
                al[mt][1] = *reinterpret_cast<const unsigned*>(&Ql[rb + 8 + g][k0 + 2*t]);
                al[mt][2] = *reinterpret_cast<const unsigned*>(&Ql[rb + g][k0 + 8 + 2*t]);
                al[mt][3] = *reinterpret_cast<const unsigned*>(&Ql[rb + 8 + g][k0 + 8 + 2*t]);
            }
            #pragma unroll
            for (int nt = 0; nt < 4; nt++) {
                int cb = wn0 + nt * 8 + g;
                bhf[nt][0] = *reinterpret_cast<const unsigned*>(&Kh[cb][k0 + 2*t]);
                bhf[nt][1] = *reinterpret_cast<const unsigned*>(&Kh[cb][k0 + 8 + 2*t]);
                blf[nt][0] = *reinterpret_cast<const unsigned*>(&Kl[cb][k0 + 2*t]);
                blf[nt][1] = *reinterpret_cast<const unsigned*>(&Kl[cb][k0 + 8 + 2*t]);
            }
            #pragma unroll
            for (int mt = 0; mt < 2; mt++)
                #pragma unroll
                for (int nt = 0; nt < 4; nt++) {
                    mma16(cS[mt][nt], ah[mt], bhf[nt]);
                    mma16(cS[mt][nt], ah[mt], blf[nt]);
                    mma16(cS[mt][nt], al[mt], bhf[nt]);
                }
        }

        // ---- mask + exp (FMA poly + MUFU split) + write attn + stage tf32 P ----
        #pragma unroll
        for (int mt = 0; mt < 2; mt++)
            #pragma unroll
            for (int nt = 0; nt < 4; nt++) {
                int tloc = wn0 + nt * 8 + 2 * t;
                int tg = T0 + tloc;
                #pragma unroll
                for (int half = 0; half < 2; half++) {
                    int rloc = wm0 + mt * 16 + half * 8 + g;
                    int sg = S0 + rloc;
                    unsigned mw = m2[rloc][tloc >> 5];
                    int sh = tloc & 31;
                    float e0 = fexp8(cS[mt][nt][half * 2]);               // FMA pipe
                    float e1 = __expf(cS[mt][nt][half * 2 + 1] * 0.125f); // MUFU pipe
                    float p0 = ((mw >> sh) & 1u)       ? e0 : 0.f;
                    float p1 = ((mw >> (sh + 1)) & 1u) ? e1 : 0.f;
                    *reinterpret_cast<float2*>(&aout[(size_t)sg * Sn + tg]) = make_float2(p0, p1);
                    *reinterpret_cast<float2*>(&Ps[rloc][tloc]) = make_float2(tf32r(p0), tf32r(p1));
                    rpart[mt][half] += p0 + p1;
                }
            }
        __syncthreads();

        // ---- heads += P @ V (tf32, operands pre-rounded; direct bit loads) ----
        #pragma unroll
        for (int kk = 0; kk < 8; kk++) {
            int k0 = kk * 8;
            unsigned a[2][4], bf[4][2];
            #pragma unroll
            for (int mt = 0; mt < 2; mt++) {
                int rb = wm0 + mt * 16;
                a[mt][0] = __float_as_uint(Ps[rb + g][k0 + t]);
                a[mt][1] = __float_as_uint(Ps[rb + 8 + g][k0 + t]);
                a[mt][2] = __float_as_uint(Ps[rb + g][k0 + t + 4]);
                a[mt][3] = __float_as_uint(Ps[rb + 8 + g][k0 + t + 4]);
            }
            #pragma unroll
            for (int nt = 0; nt < 4; nt++) {
                int cb = wn0 + nt * 8 + g;
                bf[nt][0] = __float_as_uint(Vs[k0 + t][cb]);
                bf[nt][1] = __float_as_uint(Vs[k0 + t + 4][cb]);
            }
            #pragma unroll
            for (int mt = 0; mt < 2; mt++)
                #pragma unroll
                for (int nt = 0; nt < 4; nt++)
                    mma8(cO[mt][nt], a[mt], bf[nt]);
        }
        __syncthreads();
    }

    // ---- rowsum reduce ----
    #pragma unroll
    for (int mt = 0; mt < 2; mt++)
        #pragma unroll
        for (int half = 0; half < 2; half++) {
            float v = rpart[mt][half];
            v += __shfl_xor_sync(0xffffffffu, v, 1);
            v += __shfl_xor_sync(0xffffffffu, v, 2);
            if (t == 0) atomicAdd(&rowsum[wm0 + mt * 16 + half * 8 + g], v);
        }
    __syncthreads();

    // ---- write heads (scaled by 0.25/rowsum) + rowsum ----
    float* hdst = g_heads + (size_t)bh * Sn * DHn;
    #pragma unroll
    for (int mt = 0; mt < 2; mt++)
        #pragma unroll
        for (int nt = 0; nt < 4; nt++) {
            int e = wn0 + nt * 8 + 2 * t;
            #pragma unroll
            for (int half = 0; half < 2; half++) {
                int rloc = wm0 + mt * 16 + half * 8 + g;
                float inv = 0.25f / rowsum[rloc];
                float2 val = make_float2(cO[mt][nt][half * 2] * inv, cO[mt][nt][half * 2 + 1] * inv);
                *reinterpret_cast<float2*>(&hdst[(size_t)(S0 + rloc) * DHn + e]) = val;
            }
        }
    if (tid < 128) g_rowsum[(size_t)bh * Sn + S0 + tid] = rowsum[tid];
}

// ================= Kernel 3: normalize attn rows (streaming, DRAM roofline) ======
__global__ void rescale_kernel(float* __restrict__ attn) {
    int row = blockIdx.x;
    float inv = 1.f / g_rowsum[row];
    float4* p = reinterpret_cast<float4*>(attn + (size_t)row * Sn);
    int tid = threadIdx.x;
    #pragma unroll
    for (int i = 0; i < 2; i++) {
        float4 v = p[tid + i * 256];
        v.x *= inv; v.y *= inv; v.z *= inv; v.w *= inv;
        p[tid + i * 256] = v;
    }
}

// ================= Kernel 4: out = mean_h(heads) @ Wo =================
__global__ __launch_bounds__(256) void final_kernel(
    const float* __restrict__ Wo, float* __restrict__ out)
{
    __shared__ float avg[16][64];
    int r0 = blockIdx.x * 16;
    int tid = threadIdx.x;
    #pragma unroll
    for (int it = 0; it < 4; it++) {
        int i = tid + it * 256;
        int rr = i >> 6, e = i & 63;
        int R = r0 + rr;
        int bb = R >> 11, s = R & 2047;
        size_t base = ((size_t)(bb * Hn) * Sn + s) * DHn + e;
        avg[rr][e] = g_heads[base] + g_heads[base + (size_t)Sn * DHn]
                   + g_heads[base + 2 * (size_t)Sn * DHn] + g_heads[base + 3 * (size_t)Sn * DHn];
    }
    __syncthreads();
    float acc[16];
    #pragma unroll
    for (int i = 0; i < 16; i++) acc[i] = 0.f;
    int d = tid;
    #pragma unroll 16
    for (int e = 0; e < 64; e++) {
        float w = Wo[e * Dn + d];
        #pragma unroll
        for (int i = 0; i < 16; i++) acc[i] += avg[i][e] * w;
    }
    #pragma unroll
    for (int i = 0; i < 16; i++) out[(size_t)(r0 + i) * Dn + d] = acc[i];
}

// ================= launch =================
extern "C" void kernel_launch(void* const* d_in, const int* in_sizes, int n_in,
                              void* d_out, int out_size) {
    const float* q    = (const float*)d_in[0];
    const float* k    = (const float*)d_in[1];
    const float* v    = (const float*)d_in[2];
    const int*   mask = (const int*)  d_in[3];
    const float* Wq   = (const float*)d_in[4];
    const float* Wk   = (const float*)d_in[5];
    const float* Wv   = (const float*)d_in[6];
    const float* Wo   = (const float*)d_in[7];
    float* outp  = (float*)d_out;
    float* attnp = outp + (size_t)Bn * Sn * Dn;   // outputs first, attn second

    (void)in_sizes; (void)n_in; (void)out_size;

    cudaFuncSetAttribute(attn_kernel, cudaFuncAttributeMaxDynamicSharedMemorySize, 110080);
    cudaFuncSetAttribute(attn_kernel, cudaFuncAttributePreferredSharedMemoryCarveout, 100);

    proj_pack_kernel<<<PROJ_BLOCKS + PACK_BLOCKS, 256>>>(q, k, v, Wq, Wk, Wv, mask);
    attn_kernel<<<dim3(16, 4, 8), 256, 110080>>>(attnp);
    rescale_kernel<<<Bn * Hn * Sn, 256>>>(attnp);
    final_kernel<<<(Bn * Sn) / 16, 256>>>(Wo, outp);
}

// round 8
// speedup vs baseline: 1.2751x; 1.2751x over previous
#include <cuda_runtime.h>
#include <cuda_bf16.h>

#define Bn 8
#define Sn 2048
#define Dn 256
#define Hn 4
#define DHn 64

// ---------------- scratch (static device arrays; no allocation) ----------------
__device__ __nv_bfloat16 g_qh[Bn*Hn*Sn*DHn];  // 8 MB each: pre-split Q/K (hi/lo bf16)
__device__ __nv_bfloat16 g_ql[Bn*Hn*Sn*DHn];
__device__ __nv_bfloat16 g_kh[Bn*Hn*Sn*DHn];
__device__ __nv_bfloat16 g_kl[Bn*Hn*Sn*DHn];
__device__ float g_vs[Bn*Sn*DHn];             // 4 MB  [B,S,DH], tf32-pre-rounded
__device__ float g_heads[Bn*Hn*Sn*DHn];       // 16 MB [B,H,S,DH] (carries 1/(4*rowsum))
__device__ float g_rowsum[Bn*Hn*Sn];          // 256 KB
__device__ unsigned g_mbits[Bn*Sn*(Sn/32)];   // 16.8 MB bit-packed mask

// ---------------- helpers ----------------
__device__ __forceinline__ unsigned f2tf(float x) {
    unsigned u;
    asm("cvt.rna.tf32.f32 %0, %1;" : "=r"(u) : "f"(x));
    return u;
}
__device__ __forceinline__ float tf32r(float x) { return __uint_as_float(f2tf(x)); }
__device__ __forceinline__ void mma8(float* c, const unsigned* a, const unsigned* b) {
    asm volatile("mma.sync.aligned.m16n8k8.row.col.f32.tf32.tf32.f32 "
        "{%0,%1,%2,%3}, {%4,%5,%6,%7}, {%8,%9}, {%0,%1,%2,%3};\n"
        : "+f"(c[0]), "+f"(c[1]), "+f"(c[2]), "+f"(c[3])
        : "r"(a[0]), "r"(a[1]), "r"(a[2]), "r"(a[3]), "r"(b[0]), "r"(b[1]));
}
__device__ __forceinline__ void mma16(float* c, const unsigned* a, const unsigned* b) {
    asm volatile("mma.sync.aligned.m16n8k16.row.col.f32.bf16.bf16.f32 "
        "{%0,%1,%2,%3}, {%4,%5,%6,%7}, {%8,%9}, {%0,%1,%2,%3};\n"
        : "+f"(c[0]), "+f"(c[1]), "+f"(c[2]), "+f"(c[3])
        : "r"(a[0]), "r"(a[1]), "r"(a[2]), "r"(a[3]), "r"(b[0]), "r"(b[1]));
}
__device__ __forceinline__ void bsplit(float x, __nv_bfloat16 &hi, __nv_bfloat16 &lo) {
    hi = __float2bfloat16_rn(x);
    lo = __float2bfloat16_rn(x - __bfloat162float(hi));
}

// FMA-pipe exp(s/8): magic-constant round + degree-5 poly + exponent splice. rel err ~2e-6.
__device__ __forceinline__ float fexp8(float s) {
    const float c = 0.18033688011112042f;   // log2(e)/8
    const float MAGIC = 12582912.0f;        // 1.5 * 2^23
    float t = fmaf(s, c, MAGIC);
    float k = t - MAGIC;
    float f = fmaf(s, c, -k);               // f in [-0.5, 0.5]
    float p = 1.3333558146e-3f;
    p = fmaf(p, f, 9.6181291076e-3f);
    p = fmaf(p, f, 5.5504108665e-2f);
    p = fmaf(p, f, 2.4022650696e-1f);
    p = fmaf(p, f, 6.9314718056e-1f);
    p = fmaf(p, f, 1.0f);
    int ik = __float_as_int(t) << 23;
    return __int_as_float(__float_as_int(p) + ik);
}

// ================= Kernel 0: bit-pack the mask (separate, as in R4) =================
__global__ void pack_mask_kernel(const int* __restrict__ mask) {
    size_t i = (size_t)blockIdx.x * 256 + threadIdx.x;
    int m = mask[i] != 0;
    unsigned bal = __ballot_sync(0xffffffffu, m);
    if ((threadIdx.x & 31) == 0) g_mbits[i >> 5] = bal;
}

// ================= Kernel 1: projections via bf16x3 GEMM =================
// z=0: qs = q @ Wq[h] (store bf16 hi/lo)   z=1: ks = k @ Wk[h] (store bf16 hi/lo)
// z=2: vs = v @ Wv (store tf32-rounded f32)
__global__ __launch_bounds__(256) void proj_kernel(
    const float* __restrict__ q, const float* __restrict__ k, const float* __restrict__ v,
    const float* __restrict__ Wq, const float* __restrict__ Wk, const float* __restrict__ Wv)
{
    int z = blockIdx.z;
    if (z == 2 && blockIdx.x > 0) return;
    __shared__ __nv_bfloat16 Ah[128][40];
    __shared__ __nv_bfloat16 Al[128][40];
    __shared__ __nv_bfloat16 Bh[64][40];   // stored as [n][k]
    __shared__ __nv_bfloat16 Bl[64][40];

    const float* X = (z == 0) ? q : (z == 1) ? k : v;
    const float* W = (z == 0) ? (Wq + (size_t)blockIdx.x * Dn * DHn)
                   : (z == 1) ? (Wk + (size_t)blockIdx.x * Dn * DHn) : Wv;
    int M0 = blockIdx.y * 128;
    int tid = threadIdx.x;
    int warp = tid >> 5, lane = tid & 31;
    int g = lane >> 2, t = lane & 3;
    int wm0 = (warp >> 1) * 32, wn0 = (warp & 1) * 32;

    float c[2][4][4];
    #pragma unroll
    for (int mt = 0; mt < 2; mt++)
        #pragma unroll
        for (int nt = 0; nt < 4; nt++)
            #pragma unroll
            for (int i = 0; i < 4; i++) c[mt][nt][i] = 0.f;

    for (int kc = 0; kc < 8; kc++) {
        int K0 = kc * 32;
        #pragma unroll
        for (int it = 0; it < 4; it++) {
            int i = tid + it * 256;
            int r = i >> 3, c4 = (i & 7) << 2;
            float4 val = *reinterpret_cast<const float4*>(&X[(size_t)(M0 + r) * Dn + K0 + c4]);
            __nv_bfloat16 hi, lo;
            bsplit(val.x, hi, lo); Ah[r][c4]   = hi; Al[r][c4]   = lo;
            bsplit(val.y, hi, lo); Ah[r][c4+1] = hi; Al[r][c4+1] = lo;
            bsplit(val.z, hi, lo); Ah[r][c4+2] = hi; Al[r][c4+2] = lo;
            bsplit(val.w, hi, lo); Ah[r][c4+3] = hi; Al[r][c4+3] = lo;
        }
        #pragma unroll
        for (int it = 0; it < 2; it++) {
            int i = tid + it * 256;
            int r = i >> 4, c4 = (i & 15) << 2;   // r = k row (0..31), c4 = n
            float4 val = *reinterpret_cast<const float4*>(&W[(size_t)(K0 + r) * DHn + c4]);
            __nv_bfloat16 hi, lo;
            bsplit(val.x, hi, lo); Bh[c4][r]   = hi; Bl[c4][r]   = lo;
            bsplit(val.y, hi, lo); Bh[c4+1][r] = hi; Bl[c4+1][r] = lo;
            bsplit(val.z, hi, lo); Bh[c4+2][r] = hi; Bl[c4+2][r] = lo;
            bsplit(val.w, hi, lo); Bh[c4+3][r] = hi; Bl[c4+3][r] = lo;
        }
        __syncthreads();
        #pragma unroll
        for (int kk = 0; kk < 2; kk++) {
            int k0 = kk * 16;
            unsigned ah[2][4], al[2][4], bh[4][2], bl[4][2];
            #pragma unroll
            for (int mt = 0; mt < 2; mt++) {
                int rb = wm0 + mt * 16;
                ah[mt][0] = *reinterpret_cast<const unsigned*>(&Ah[rb + g][k0 + 2*t]);
                ah[mt][1] = *reinterpret_cast<const unsigned*>(&Ah[rb + 8 + g][k0 + 2*t]);
                ah[mt][2] = *reinterpret_cast<const unsigned*>(&Ah[rb + g][k0 + 8 + 2*t]);
                ah[mt][3] = *reinterpret_cast<const unsigned*>(&Ah[rb + 8 + g][k0 + 8 + 2*t]);
                al[mt][0] = *reinterpret_cast<const unsigned*>(&Al[rb + g][k0 + 2*t]);
                al[mt][1] = *reinterpret_cast<const unsigned*>(&Al[rb + 8 + g][k0 + 2*t]);
                al[mt][2] = *reinterpret_cast<const unsigned*>(&Al[rb + g][k0 + 8 + 2*t]);
                al[mt][3] = *reinterpret_cast<const unsigned*>(&Al[rb + 8 + g][k0 + 8 + 2*t]);
            }
            #pragma unroll
            for (int nt = 0; nt < 4; nt++) {
                int cb = wn0 + nt * 8 + g;
                bh[nt][0] = *reinterpret_cast<const unsigned*>(&Bh[cb][k0 + 2*t]);
                bh[nt][1] = *reinterpret_cast<const unsigned*>(&Bh[cb][k0 + 8 + 2*t]);
                bl[nt][0] = *reinterpret_cast<const unsigned*>(&Bl[cb][k0 + 2*t]);
                bl[nt][1] = *reinterpret_cast<const unsigned*>(&Bl[cb][k0 + 8 + 2*t]);
            }
            #pragma unroll
            for (int mt = 0; mt < 2; mt++)
                #pragma unroll
                for (int nt = 0; nt < 4; nt++) {
                    mma16(c[mt][nt], ah[mt], bh[nt]);
                    mma16(c[mt][nt], ah[mt], bl[nt]);
                    mma16(c[mt][nt], al[mt], bh[nt]);
                }
        }
        __syncthreads();
    }
    #pragma unroll
    for (int mt = 0; mt < 2; mt++)
        #pragma unroll
        for (int nt = 0; nt < 4; nt++) {
            int e = wn0 + nt * 8 + 2 * t;
            #pragma unroll
            for (int half = 0; half < 2; half++) {
                int r = M0 + wm0 + mt * 16 + half * 8 + g;
                int bb = r >> 11, s = r & 2047;
                float v0 = c[mt][nt][half * 2], v1 = c[mt][nt][half * 2 + 1];
                if (z == 2) {
                    *reinterpret_cast<float2*>(&g_vs[((size_t)bb * Sn + s) * DHn + e]) =
                        make_float2(tf32r(v0), tf32r(v1));
                } else {
                    int h = blockIdx.x;
                    size_t idx = (((size_t)(bb * Hn + h)) * Sn + s) * DHn + e;
                    __nv_bfloat16 h0, l0, h1, l1;
                    bsplit(v0, h0, l0); bsplit(v1, h1, l1);
                    __nv_bfloat162 vh; vh.x = h0; vh.y = h1;
                    __nv_bfloat162 vl; vl.x = l0; vl.y = l1;
                    if (z == 0) {
                        *reinterpret_cast<__nv_bfloat162*>(&g_qh[idx]) = vh;
                        *reinterpret_cast<__nv_bfloat162*>(&g_ql[idx]) = vl;
                    } else {
                        *reinterpret_cast<__nv_bfloat162*>(&g_kh[idx]) = vh;
                        *reinterpret_cast<__nv_bfloat162*>(&g_kl[idx]) = vl;
                    }
                }
            }
        }
}

// ================= Kernel 2: fused attention =================
// QK^T via bf16x3 (pre-split operands, copy-only staging), PV via tf32 (pre-rounded,
// raw bit loads). exp via FMA-pipe polynomial for both elements (R4-proven path).
__global__ __launch_bounds__(256) void attn_kernel(float* __restrict__ attn_out)
{
    extern __shared__ char smraw[];
    __nv_bfloat16 (*Qh)[72] = reinterpret_cast<__nv_bfloat16(*)[72]>(smraw);            // 128x72
    __nv_bfloat16 (*Ql)[72] = reinterpret_cast<__nv_bfloat16(*)[72]>(smraw + 18432);
    __nv_bfloat16 (*Kh)[72] = reinterpret_cast<__nv_bfloat16(*)[72]>(smraw + 36864);    // 64x72
    __nv_bfloat16 (*Kl)[72] = reinterpret_cast<__nv_bfloat16(*)[72]>(smraw + 46080);
    float (*Vs)[72] = reinterpret_cast<float(*)[72]>(smraw + 55296);                    // 64x72 f32
    float (*Ps)[68] = reinterpret_cast<float(*)[68]>(smraw + 73728);                    // 128x68 f32
    unsigned (*m2)[2] = reinterpret_cast<unsigned(*)[2]>(smraw + 108544);               // 128x2
    float* rowsum = reinterpret_cast<float*>(smraw + 109568);                           // 128

    int st = blockIdx.x, h = blockIdx.y, b = blockIdx.z;
    int bh = b * Hn + h;
    int S0 = st * 128;
    int tid = threadIdx.x, warp = tid >> 5, lane = tid & 31;
    int g = lane >> 2, t = lane & 3;
    int wm0 = (warp >> 1) * 32, wn0 = (warp & 1) * 32;

    const __nv_bfloat16* qh_src = g_qh + ((size_t)bh * Sn + S0) * DHn;
    const __nv_bfloat16* ql_src = g_ql + ((size_t)bh * Sn + S0) * DHn;
    const __nv_bfloat16* kh_src = g_kh + (size_t)bh * Sn * DHn;
    const __nv_bfloat16* kl_src = g_kl + (size_t)bh * Sn * DHn;
    const float* vsrc = g_vs + (size_t)b * Sn * DHn;
    const unsigned* msrc = g_mbits + ((size_t)b * Sn + S0) * (Sn / 32);
    float* aout = attn_out + (size_t)bh * Sn * Sn;

    // stage Q hi/lo (pure copies, no cvt)
    #pragma unroll
    for (int it = 0; it < 4; it++) {
        int i = tid + it * 256;
        int r = i >> 3, c8 = (i & 7) << 3;
        *reinterpret_cast<uint4*>(&Qh[r][c8]) =
            *reinterpret_cast<const uint4*>(&qh_src[(size_t)r * DHn + c8]);
        *reinterpret_cast<uint4*>(&Ql[r][c8]) =
            *reinterpret_cast<const uint4*>(&ql_src[(size_t)r * DHn + c8]);
    }
    if (tid < 128) rowsum[tid] = 0.f;

    float cO[2][4][4];
    #pragma unroll
    for (int mt = 0; mt < 2; mt++)
        #pragma unroll
        for (int nt = 0; nt < 4; nt++)
            #pragma unroll
            for (int i = 0; i < 4; i++) cO[mt][nt][i] = 0.f;
    float rpart[2][2] = {{0.f, 0.f}, {0.f, 0.f}};

    for (int tc = 0; tc < 32; tc++) {
        int T0 = tc * 64;
        // stage K hi/lo (copies) + V (pre-rounded f32) + mask words
        #pragma unroll
        for (int it = 0; it < 2; it++) {
            int i = tid + it * 256;
            int r = i >> 3, c8 = (i & 7) << 3;
            *reinterpret_cast<uint4*>(&Kh[r][c8]) =
                *reinterpret_cast<const uint4*>(&kh_src[(size_t)(T0 + r) * DHn + c8]);
            *reinterpret_cast<uint4*>(&Kl[r][c8]) =
                *reinterpret_cast<const uint4*>(&kl_src[(size_t)(T0 + r) * DHn + c8]);
        }
        #pragma unroll
        for (int it = 0; it < 4; it++) {
            int i = tid + it * 256;
            int r = i >> 4, c4 = (i & 15) << 2;
            float4 vv = *reinterpret_cast<const float4*>(&vsrc[(size_t)(T0 + r) * DHn + c4]);
            Vs[r][c4] = vv.x; Vs[r][c4+1] = vv.y; Vs[r][c4+2] = vv.z; Vs[r][c4+3] = vv.w;
        }
        { // 128 rows x 2 mask words
            int r = tid >> 1, w = tid & 1;
            m2[r][w] = msrc[(size_t)r * (Sn / 32) + (T0 >> 5) + w];
        }
        __syncthreads();

        // ---- QK^T (bf16x3) ----
        float cS[2][4][4];
        #pragma unroll
        for (int mt = 0; mt < 2; mt++)
            #pragma unroll
            for (int nt = 0; nt < 4; nt++)
                #pragma unroll
                for (int i = 0; i < 4; i++) cS[mt][nt][i] = 0.f;
        #pragma unroll
        for (int kk = 0; kk < 4; kk++) {
            int k0 = kk * 16;
            unsigned ah[2][4], al[2][4], bhf[4][2], blf[4][2];
            #pragma unroll
            for (int mt = 0; mt < 2; mt++) {
                int rb = wm0 + mt * 16;
                ah[mt][0] = *reinterpret_cast<const unsigned*>(&Qh[rb + g][k0 + 2*t]);
                ah[mt][1] = *reinterpret_cast<const unsigned*>(&Qh[rb + 8 + g][k0 + 2*t]);
                ah[mt][2] = *reinterpret_cast<const unsigned*>(&Qh[rb + g][k0 + 8 + 2*t]);
                ah[mt][3] = *reinterpret_cast<const unsigned*>(&Qh[rb + 8 + g][k0 + 8 + 2*t]);
                al[mt][0] = *reinterpret_cast<const unsigned*>(&Ql[rb + g][k0 + 2*t]);
                al[mt][1] = *reinterpret_cast<const unsigned*>(&Ql[rb + 8 + g][k0 + 2*t]);
                al[mt][2] = *reinterpret_cast<const unsigned*>(&Ql[rb + g][k0 + 8 + 2*t]);
                al[mt][3] = *reinterpret_cast<const unsigned*>(&Ql[rb + 8 + g][k0 + 8 + 2*t]);
            }
            #pragma unroll
            for (int nt = 0; nt < 4; nt++) {
                int cb = wn0 + nt * 8 + g;
                bhf[nt][0] = *reinterpret_cast<const unsigned*>(&Kh[cb][k0 + 2*t]);
                bhf[nt][1] = *reinterpret_cast<const unsigned*>(&Kh[cb][k0 + 8 + 2*t]);
                blf[nt][0] = *reinterpret_cast<const unsigned*>(&Kl[cb][k0 + 2*t]);
                blf[nt][1] = *reinterpret_cast<const unsigned*>(&Kl[cb][k0 + 8 + 2*t]);
            }
            #pragma unroll
            for (int mt = 0; mt < 2; mt++)
                #pragma unroll
                for (int nt = 0; nt < 4; nt++) {
                    mma16(cS[mt][nt], ah[mt], bhf[nt]);
                    mma16(cS[mt][nt], ah[mt], blf[nt]);
                    mma16(cS[mt][nt], al[mt], bhf[nt]);
                }
        }

        // ---- mask + exp (FMA pipe, both) + write attn + stage tf32 P ----
        #pragma unroll
        for (int mt = 0; mt < 2; mt++)
            #pragma unroll
            for (int nt = 0; nt < 4; nt++) {
                int tloc = wn0 + nt * 8 + 2 * t;
                int tg = T0 + tloc;
                #pragma unroll
                for (int half = 0; half < 2; half++) {
                    int rloc = wm0 + mt * 16 + half * 8 + g;
                    int sg = S0 + rloc;
                    unsigned mw = m2[rloc][tloc >> 5];
                    int sh = tloc & 31;
                    float e0 = fexp8(cS[mt][nt][half * 2]);
                    float e1 = fexp8(cS[mt][nt][half * 2 + 1]);
                    float p0 = ((mw >> sh) & 1u)       ? e0 : 0.f;
                    float p1 = ((mw >> (sh + 1)) & 1u) ? e1 : 0.f;
                    *reinterpret_cast<float2*>(&aout[(size_t)sg * Sn + tg]) = make_float2(p0, p1);
                    *reinterpret_cast<float2*>(&Ps[rloc][tloc]) = make_float2(tf32r(p0), tf32r(p1));
                    rpart[mt][half] += p0 + p1;
                }
            }
        __syncthreads();

        // ---- heads += P @ V (tf32, operands pre-rounded; direct bit loads) ----
        #pragma unroll
        for (int kk = 0; kk < 8; kk++) {
            int k0 = kk * 8;
            unsigned a[2][4], bf[4][2];
            #pragma unroll
            for (int mt = 0; mt < 2; mt++) {
                int rb = wm0 + mt * 16;
                a[mt][0] = __float_as_uint(Ps[rb + g][k0 + t]);
                a[mt][1] = __float_as_uint(Ps[rb + 8 + g][k0 + t]);
                a[mt][2] = __float_as_uint(Ps[rb + g][k0 + t + 4]);
                a[mt][3] = __float_as_uint(Ps[rb + 8 + g][k0 + t + 4]);
            }
            #pragma unroll
            for (int nt = 0; nt < 4; nt++) {
                int cb = wn0 + nt * 8 + g;
                bf[nt][0] = __float_as_uint(Vs[k0 + t][cb]);
                bf[nt][1] = __float_as_uint(Vs[k0 + t + 4][cb]);
            }
            #pragma unroll
            for (int mt = 0; mt < 2; mt++)
                #pragma unroll
                for (int nt = 0; nt < 4; nt++)
                    mma8(cO[mt][nt], a[mt], bf[nt]);
        }
        __syncthreads();
    }

    // ---- rowsum reduce ----
    #pragma unroll
    for (int mt = 0; mt < 2; mt++)
        #pragma unroll
        for (int half = 0; half < 2; half++) {
            float v = rpart[mt][half];
            v += __shfl_xor_sync(0xffffffffu, v, 1);
            v += __shfl_xor_sync(0xffffffffu, v, 2);
            if (t == 0) atomicAdd(&rowsum[wm0 + mt * 16 + half * 8 + g], v);
        }
    __syncthreads();

    // ---- write heads (scaled by 0.25/rowsum) + rowsum ----
    float* hdst = g_heads + (size_t)bh * Sn * DHn;
    #pragma unroll
    for (int mt = 0; mt < 2; mt++)
        #pragma unroll
        for (int nt = 0; nt < 4; nt++) {
            int e = wn0 + nt * 8 + 2 * t;
            #pragma unroll
            for (int half = 0; half < 2; half++) {
                int rloc = wm0 + mt * 16 + half * 8 + g;
                float inv = 0.25f / rowsum[rloc];
                float2 val = make_float2(cO[mt][nt][half * 2] * inv, cO[mt][nt][half * 2 + 1] * inv);
                *reinterpret_cast<float2*>(&hdst[(size_t)(S0 + rloc) * DHn + e]) = val;
            }
        }
    if (tid < 128) g_rowsum[(size_t)bh * Sn + S0 + tid] = rowsum[tid];
}

// ================= Kernel 3: normalize attn rows (streaming, DRAM roofline) ======
__global__ void rescale_kernel(float* __restrict__ attn) {
    int row = blockIdx.x;
    float inv = 1.f / g_rowsum[row];
    float4* p = reinterpret_cast<float4*>(attn + (size_t)row * Sn);
    int tid = threadIdx.x;
    #pragma unroll
    for (int i = 0; i < 2; i++) {
        float4 v = p[tid + i * 256];
        v.x *= inv; v.y *= inv; v.z *= inv; v.w *= inv;
        p[tid + i * 256] = v;
    }
}

// ================= Kernel 4: out = mean_h(heads) @ Wo =================
__global__ __launch_bounds__(256) void final_kernel(
    const float* __restrict__ Wo, float* __restrict__ out)
{
    __shared__ float avg[16][64];
    int r0 = blockIdx.x * 16;
    int tid = threadIdx.x;
    #pragma unroll
    for (int it = 0; it < 4; it++) {
        int i = tid + it * 256;
        int rr = i >> 6, e = i & 63;
        int R = r0 + rr;
        int bb = R >> 11, s = R & 2047;
        size_t base = ((size_t)(bb * Hn) * Sn + s) * DHn + e;
        avg[rr][e] = g_heads[base] + g_heads[base + (size_t)Sn * DHn]
                   + g_heads[base + 2 * (size_t)Sn * DHn] + g_heads[base + 3 * (size_t)Sn * DHn];
    }
    __syncthreads();
    float acc[16];
    #pragma unroll
    for (int i = 0; i < 16; i++) acc[i] = 0.f;
    int d = tid;
    #pragma unroll 16
    for (int e = 0; e < 64; e++) {
        float w = Wo[e * Dn + d];
        #pragma unroll
        for (int i = 0; i < 16; i++) acc[i] += avg[i][e] * w;
    }
    #pragma unroll
    for (int i = 0; i < 16; i++) out[(size_t)(r0 + i) * Dn + d] = acc[i];
}

// ================= launch =================
extern "C" void kernel_launch(void* const* d_in, const int* in_sizes, int n_in,
                              void* d_out, int out_size) {
    const float* q    = (const float*)d_in[0];
    const float* k    = (const float*)d_in[1];
    const float* v    = (const float*)d_in[2];
    const int*   mask = (const int*)  d_in[3];
    const float* Wq   = (const float*)d_in[4];
    const float* Wk   = (const float*)d_in[5];
    const float* Wv   = (const float*)d_in[6];
    const float* Wo   = (const float*)d_in[7];
    float* outp  = (float*)d_out;
    float* attnp = outp + (size_t)Bn * Sn * Dn;   // outputs first, attn second

    (void)in_sizes; (void)n_in; (void)out_size;

    cudaFuncSetAttribute(attn_kernel, cudaFuncAttributeMaxDynamicSharedMemorySize, 110080);

    pack_mask_kernel<<<(Bn * Sn * Sn) / 256, 256>>>(mask);
    proj_kernel<<<dim3(4, 128, 3), 256>>>(q, k, v, Wq, Wk, Wv);
    attn_kernel<<<dim3(16, 4, 8), 256, 110080>>>(attnp);
    rescale_kernel<<<Bn * Hn * Sn, 256>>>(attnp);
    final_kernel<<<(Bn * Sn) / 16, 256>>>(Wo, outp);
}

// round 9
// speedup vs baseline: 1.3413x; 1.0519x over previous
#include <cuda_runtime.h>
#include <cuda_bf16.h>

#define Bn 8
#define Sn 2048
#define Dn 256
#define Hn 4
#define DHn 64

// ---------------- scratch (static device arrays; no allocation) ----------------
__device__ float g_qs[Bn*Hn*Sn*DHn];     // 16 MB  [B,H,S,DH]  tf32-pre-rounded
__device__ float g_ks[Bn*Hn*Sn*DHn];     // 16 MB  [B,H,S,DH]  tf32-pre-rounded
__device__ float g_vs[Bn*Sn*DHn];        //  4 MB  [B,S,DH]    tf32-pre-rounded
__device__ float g_heads[Bn*Hn*Sn*DHn];  // 16 MB  [B,H,S,DH]  (carries 1/(4*rowsum))
__device__ float g_rowsum[Bn*Hn*Sn];     // 256 KB
__device__ unsigned g_mbits[Bn*Sn*(Sn/32)]; // 16.8 MB bit-packed mask

// ---------------- helpers ----------------
__device__ __forceinline__ unsigned f2tf(float x) {
    unsigned u;
    asm("cvt.rna.tf32.f32 %0, %1;" : "=r"(u) : "f"(x));
    return u;
}
__device__ __forceinline__ float tf32r(float x) { return __uint_as_float(f2tf(x)); }
__device__ __forceinline__ void mma8(float* c, const unsigned* a, const unsigned* b) {
    asm volatile("mma.sync.aligned.m16n8k8.row.col.f32.tf32.tf32.f32 "
        "{%0,%1,%2,%3}, {%4,%5,%6,%7}, {%8,%9}, {%0,%1,%2,%3};\n"
        : "+f"(c[0]), "+f"(c[1]), "+f"(c[2]), "+f"(c[3])
        : "r"(a[0]), "r"(a[1]), "r"(a[2]), "r"(a[3]), "r"(b[0]), "r"(b[1]));
}
__device__ __forceinline__ void mma16(float* c, const unsigned* a, const unsigned* b) {
    asm volatile("mma.sync.aligned.m16n8k16.row.col.f32.bf16.bf16.f32 "
        "{%0,%1,%2,%3}, {%4,%5,%6,%7}, {%8,%9}, {%0,%1,%2,%3};\n"
        : "+f"(c[0]), "+f"(c[1]), "+f"(c[2]), "+f"(c[3])
        : "r"(a[0]), "r"(a[1]), "r"(a[2]), "r"(a[3]), "r"(b[0]), "r"(b[1]));
}
__device__ __forceinline__ void bsplit(float x, __nv_bfloat16 &hi, __nv_bfloat16 &lo) {
    hi = __float2bfloat16_rn(x);
    lo = __float2bfloat16_rn(x - __bfloat162float(hi));
}

// FMA-pipe exp(s/8): magic-constant round + degree-5 poly + exponent splice. rel err ~2e-6.
__device__ __forceinline__ float fexp8(float s) {
    const float c = 0.18033688011112042f;   // log2(e)/8
    const float MAGIC = 12582912.0f;        // 1.5 * 2^23
    float t = fmaf(s, c, MAGIC);
    float k = t - MAGIC;
    float f = fmaf(s, c, -k);               // f in [-0.5, 0.5]
    float p = 1.3333558146e-3f;
    p = fmaf(p, f, 9.6181291076e-3f);
    p = fmaf(p, f, 5.5504108665e-2f);
    p = fmaf(p, f, 2.4022650696e-1f);
    p = fmaf(p, f, 6.9314718056e-1f);
    p = fmaf(p, f, 1.0f);
    int ik = __float_as_int(t) << 23;
    return __int_as_float(__float_as_int(p) + ik);
}

// ================= Kernel 0: bit-pack the mask =================
__global__ void pack_mask_kernel(const int* __restrict__ mask) {
    size_t i = (size_t)blockIdx.x * 256 + threadIdx.x;
    int m = mask[i] != 0;
    unsigned bal = __ballot_sync(0xffffffffu, m);
    if ((threadIdx.x & 31) == 0) g_mbits[i >> 5] = bal;
}

// ================= Kernel 1: projections via bf16x3 GEMM, tf32-rounded outputs ====
// z=0: qs = q @ Wq[h]   z=1: ks = k @ Wk[h]   z=2: vs = v @ Wv
__global__ __launch_bounds__(256) void proj_kernel(
    const float* __restrict__ q, const float* __restrict__ k, const float* __restrict__ v,
    const float* __restrict__ Wq, const float* __restrict__ Wk, const float* __restrict__ Wv)
{
    int z = blockIdx.z;
    if (z == 2 && blockIdx.x > 0) return;
    __shared__ __nv_bfloat16 Ah[128][40];
    __shared__ __nv_bfloat16 Al[128][40];
    __shared__ __nv_bfloat16 Bh[64][40];   // stored as [n][k]
    __shared__ __nv_bfloat16 Bl[64][40];

    const float* X = (z == 0) ? q : (z == 1) ? k : v;
    const float* W = (z == 0) ? (Wq + (size_t)blockIdx.x * Dn * DHn)
                   : (z == 1) ? (Wk + (size_t)blockIdx.x * Dn * DHn) : Wv;
    int M0 = blockIdx.y * 128;
    int tid = threadIdx.x;
    int warp = tid >> 5, lane = tid & 31;
    int g = lane >> 2, t = lane & 3;
    int wm0 = (warp >> 1) * 32, wn0 = (warp & 1) * 32;

    float c[2][4][4];
    #pragma unroll
    for (int mt = 0; mt < 2; mt++)
        #pragma unroll
        for (int nt = 0; nt < 4; nt++)
            #pragma unroll
            for (int i = 0; i < 4; i++) c[mt][nt][i] = 0.f;

    for (int kc = 0; kc < 8; kc++) {
        int K0 = kc * 32;
        #pragma unroll
        for (int it = 0; it < 4; it++) {
            int i = tid + it * 256;
            int r = i >> 3, c4 = (i & 7) << 2;
            float4 val = *reinterpret_cast<const float4*>(&X[(size_t)(M0 + r) * Dn + K0 + c4]);
            __nv_bfloat16 hi, lo;
            bsplit(val.x, hi, lo); Ah[r][c4]   = hi; Al[r][c4]   = lo;
            bsplit(val.y, hi, lo); Ah[r][c4+1] = hi; Al[r][c4+1] = lo;
            bsplit(val.z, hi, lo); Ah[r][c4+2] = hi; Al[r][c4+2] = lo;
            bsplit(val.w, hi, lo); Ah[r][c4+3] = hi; Al[r][c4+3] = lo;
        }
        #pragma unroll
        for (int it = 0; it < 2; it++) {
            int i = tid + it * 256;
            int r = i >> 4, c4 = (i & 15) << 2;   // r = k row (0..31), c4 = n
            float4 val = *reinterpret_cast<const float4*>(&W[(size_t)(K0 + r) * DHn + c4]);
            __nv_bfloat16 hi, lo;
            bsplit(val.x, hi, lo); Bh[c4][r]   = hi; Bl[c4][r]   = lo;
            bsplit(val.y, hi, lo); Bh[c4+1][r] = hi; Bl[c4+1][r] = lo;
            bsplit(val.z, hi, lo); Bh[c4+2][r] = hi; Bl[c4+2][r] = lo;
            bsplit(val.w, hi, lo); Bh[c4+3][r] = hi; Bl[c4+3][r] = lo;
        }
        __syncthreads();
        #pragma unroll
        for (int kk = 0; kk < 2; kk++) {
            int k0 = kk * 16;
            unsigned ah[2][4], al[2][4], bh[4][2], bl[4][2];
            #pragma unroll
            for (int mt = 0; mt < 2; mt++) {
                int rb = wm0 + mt * 16;
                ah[mt][0] = *reinterpret_cast<const unsigned*>(&Ah[rb + g][k0 + 2*t]);
                ah[mt][1] = *reinterpret_cast<const unsigned*>(&Ah[rb + 8 + g][k0 + 2*t]);
                ah[mt][2] = *reinterpret_cast<const unsigned*>(&Ah[rb + g][k0 + 8 + 2*t]);
                ah[mt][3] = *reinterpret_cast<const unsigned*>(&Ah[rb + 8 + g][k0 + 8 + 2*t]);
                al[mt][0] = *reinterpret_cast<const unsigned*>(&Al[rb + g][k0 + 2*t]);
                al[mt][1] = *reinterpret_cast<const unsigned*>(&Al[rb + 8 + g][k0 + 2*t]);
                al[mt][2] = *reinterpret_cast<const unsigned*>(&Al[rb + g][k0 + 8 + 2*t]);
                al[mt][3] = *reinterpret_cast<const unsigned*>(&Al[rb + 8 + g][k0 + 8 + 2*t]);
            }
            #pragma unroll
            for (int nt = 0; nt < 4; nt++) {
                int cb = wn0 + nt * 8 + g;
                bh[nt][0] = *reinterpret_cast<const unsigned*>(&Bh[cb][k0 + 2*t]);
                bh[nt][1] = *reinterpret_cast<const unsigned*>(&Bh[cb][k0 + 8 + 2*t]);
                bl[nt][0] = *reinterpret_cast<const unsigned*>(&Bl[cb][k0 + 2*t]);
                bl[nt][1] = *reinterpret_cast<const unsigned*>(&Bl[cb][k0 + 8 + 2*t]);
            }
            #pragma unroll
            for (int mt = 0; mt < 2; mt++)
                #pragma unroll
                for (int nt = 0; nt < 4; nt++) {
                    mma16(c[mt][nt], ah[mt], bh[nt]);
                    mma16(c[mt][nt], ah[mt], bl[nt]);
                    mma16(c[mt][nt], al[mt], bh[nt]);
                }
        }
        __syncthreads();
    }
    #pragma unroll
    for (int mt = 0; mt < 2; mt++)
        #pragma unroll
        for (int nt = 0; nt < 4; nt++) {
            int e = wn0 + nt * 8 + 2 * t;
            #pragma unroll
            for (int half = 0; half < 2; half++) {
                int r = M0 + wm0 + mt * 16 + half * 8 + g;
                int bb = r >> 11, s = r & 2047;
                float2 val = make_float2(tf32r(c[mt][nt][half * 2]), tf32r(c[mt][nt][half * 2 + 1]));
                if (z == 2) {
                    *reinterpret_cast<float2*>(&g_vs[((size_t)bb * Sn + s) * DHn + e]) = val;
                } else {
                    float* dst = (z == 0) ? g_qs : g_ks;
                    int h = blockIdx.x;
                    *reinterpret_cast<float2*>(&dst[(((size_t)(bb * Hn + h)) * Sn + s) * DHn + e]) = val;
                }
            }
        }
}

// ================= Kernel 2: fused attention =================
// QK^T via single tf32 (operands pre-rounded in gmem; staging is pure copies),
// PV via tf32 (pre-rounded; raw bit loads). exp via FMA-pipe polynomial.
__global__ __launch_bounds__(256) void attn_kernel(float* __restrict__ attn_out)
{
    extern __shared__ char smraw[];
    float (*Qs)[68] = reinterpret_cast<float(*)[68]>(smraw);                  // 128x68
    float (*Ks)[68] = reinterpret_cast<float(*)[68]>(smraw + 34816);          // 64x68
    float (*Vs)[72] = reinterpret_cast<float(*)[72]>(smraw + 52224);          // 64x72
    float (*Ps)[68] = reinterpret_cast<float(*)[68]>(smraw + 70656);          // 128x68
    unsigned (*m2)[2] = reinterpret_cast<unsigned(*)[2]>(smraw + 105472);     // 128x2
    float* rowsum = reinterpret_cast<float*>(smraw + 106496);                 // 128

    int st = blockIdx.x, h = blockIdx.y, b = blockIdx.z;
    int bh = b * Hn + h;
    int S0 = st * 128;
    int tid = threadIdx.x, warp = tid >> 5, lane = tid & 31;
    int g = lane >> 2, t = lane & 3;
    int wm0 = (warp >> 1) * 32, wn0 = (warp & 1) * 32;

    const float* qsrc = g_qs + ((size_t)bh * Sn + S0) * DHn;
    const float* ksrc = g_ks + (size_t)bh * Sn * DHn;
    const float* vsrc = g_vs + (size_t)b * Sn * DHn;
    const unsigned* msrc = g_mbits + ((size_t)b * Sn + S0) * (Sn / 32);
    float* aout = attn_out + (size_t)bh * Sn * Sn;

    // stage Q (pure copies — already tf32-rounded)
    #pragma unroll
    for (int it = 0; it < 8; it++) {
        int i = tid + it * 256;
        int r = i >> 4, c4 = (i & 15) << 2;
        float4 val = *reinterpret_cast<const float4*>(&qsrc[(size_t)r * DHn + c4]);
        Qs[r][c4] = val.x; Qs[r][c4+1] = val.y; Qs[r][c4+2] = val.z; Qs[r][c4+3] = val.w;
    }
    if (tid < 128) rowsum[tid] = 0.f;

    float cO[2][4][4];
    #pragma unroll
    for (int mt = 0; mt < 2; mt++)
        #pragma unroll
        for (int nt = 0; nt < 4; nt++)
            #pragma unroll
            for (int i = 0; i < 4; i++) cO[mt][nt][i] = 0.f;
    float rpart[2][2] = {{0.f, 0.f}, {0.f, 0.f}};

    for (int tc = 0; tc < 32; tc++) {
        int T0 = tc * 64;
        // stage K + V (pure copies) + mask words
        #pragma unroll
        for (int it = 0; it < 4; it++) {
            int i = tid + it * 256;
            int r = i >> 4, c4 = (i & 15) << 2;
            float4 kv = *reinterpret_cast<const float4*>(&ksrc[(size_t)(T0 + r) * DHn + c4]);
            Ks[r][c4] = kv.x; Ks[r][c4+1] = kv.y; Ks[r][c4+2] = kv.z; Ks[r][c4+3] = kv.w;
            float4 vv = *reinterpret_cast<const float4*>(&vsrc[(size_t)(T0 + r) * DHn + c4]);
            Vs[r][c4] = vv.x; Vs[r][c4+1] = vv.y; Vs[r][c4+2] = vv.z; Vs[r][c4+3] = vv.w;
        }
        { // 128 rows x 2 mask words
            int r = tid >> 1, w = tid & 1;
            m2[r][w] = msrc[(size_t)r * (Sn / 32) + (T0 >> 5) + w];
        }
        __syncthreads();

        // ---- QK^T (tf32 x1, 64 mma8 per tile) ----
        float cS[2][4][4];
        #pragma unroll
        for (int mt = 0; mt < 2; mt++)
            #pragma unroll
            for (int nt = 0; nt < 4; nt++)
                #pragma unroll
                for (int i = 0; i < 4; i++) cS[mt][nt][i] = 0.f;
        #pragma unroll
        for (int kk = 0; kk < 8; kk++) {
            int k0 = kk * 8;
            unsigned a[2][4], bf[4][2];
            #pragma unroll
            for (int mt = 0; mt < 2; mt++) {
                int rb = wm0 + mt * 16;
                a[mt][0] = __float_as_uint(Qs[rb + g][k0 + t]);
                a[mt][1] = __float_as_uint(Qs[rb + 8 + g][k0 + t]);
                a[mt][2] = __float_as_uint(Qs[rb + g][k0 + t + 4]);
                a[mt][3] = __float_as_uint(Qs[rb + 8 + g][k0 + t + 4]);
            }
            #pragma unroll
            for (int nt = 0; nt < 4; nt++) {
                int cb = wn0 + nt * 8 + g;
                bf[nt][0] = __float_as_uint(Ks[cb][k0 + t]);
                bf[nt][1] = __float_as_uint(Ks[cb][k0 + t + 4]);
            }
            #pragma unroll
            for (int mt = 0; mt < 2; mt++)
                #pragma unroll
                for (int nt = 0; nt < 4; nt++)
                    mma8(cS[mt][nt], a[mt], bf[nt]);
        }

        // ---- mask + exp (FMA pipe) + write attn + stage tf32 P ----
        #pragma unroll
        for (int mt = 0; mt < 2; mt++)
            #pragma unroll
            for (int nt = 0; nt < 4; nt++) {
                int tloc = wn0 + nt * 8 + 2 * t;
                int tg = T0 + tloc;
                #pragma unroll
                for (int half = 0; half < 2; half++) {
                    int rloc = wm0 + mt * 16 + half * 8 + g;
                    int sg = S0 + rloc;
                    unsigned mw = m2[rloc][tloc >> 5];
                    int sh = tloc & 31;
                    float e0 = fexp8(cS[mt][nt][half * 2]);
                    float e1 = fexp8(cS[mt][nt][half * 2 + 1]);
                    float p0 = ((mw >> sh) & 1u)       ? e0 : 0.f;
                    float p1 = ((mw >> (sh + 1)) & 1u) ? e1 : 0.f;
                    *reinterpret_cast<float2*>(&aout[(size_t)sg * Sn + tg]) = make_float2(p0, p1);
                    *reinterpret_cast<float2*>(&Ps[rloc][tloc]) = make_float2(tf32r(p0), tf32r(p1));
                    rpart[mt][half] += p0 + p1;
                }
            }
        __syncthreads();

        // ---- heads += P @ V (tf32, operands pre-rounded; raw bit loads) ----
        #pragma unroll
        for (int kk = 0; kk < 8; kk++) {
            int k0 = kk * 8;
            unsigned a[2][4], bf[4][2];
            #pragma unroll
            for (int mt = 0; mt < 2; mt++) {
                int rb = wm0 + mt * 16;
                a[mt][0] = __float_as_uint(Ps[rb + g][k0 + t]);
                a[mt][1] = __float_as_uint(Ps[rb + 8 + g][k0 + t]);
                a[mt][2] = __float_as_uint(Ps[rb + g][k0 + t + 4]);
                a[mt][3] = __float_as_uint(Ps[rb + 8 + g][k0 + t + 4]);
            }
            #pragma unroll
            for (int nt = 0; nt < 4; nt++) {
                int cb = wn0 + nt * 8 + g;
                bf[nt][0] = __float_as_uint(Vs[k0 + t][cb]);
                bf[nt][1] = __float_as_uint(Vs[k0 + t + 4][cb]);
            }
            #pragma unroll
            for (int mt = 0; mt < 2; mt++)
                #pragma unroll
                for (int nt = 0; nt < 4; nt++)
                    mma8(cO[mt][nt], a[mt], bf[nt]);
        }
        __syncthreads();
    }

    // ---- rowsum reduce ----
    #pragma unroll
    for (int mt = 0; mt < 2; mt++)
        #pragma unroll
        for (int half = 0; half < 2; half++) {
            float v = rpart[mt][half];
            v += __shfl_xor_sync(0xffffffffu, v, 1);
            v += __shfl_xor_sync(0xffffffffu, v, 2);
            if (t == 0) atomicAdd(&rowsum[wm0 + mt * 16 + half * 8 + g], v);
        }
    __syncthreads();

    // ---- write heads (scaled by 0.25/rowsum) + rowsum ----
    float* hdst = g_heads + (size_t)bh * Sn * DHn;
    #pragma unroll
    for (int mt = 0; mt < 2; mt++)
        #pragma unroll
        for (int nt = 0; nt < 4; nt++) {
            int e = wn0 + nt * 8 + 2 * t;
            #pragma unroll
            for (int half = 0; half < 2; half++) {
                int rloc = wm0 + mt * 16 + half * 8 + g;
                float inv = 0.25f / rowsum[rloc];
                float2 val = make_float2(cO[mt][nt][half * 2] * inv, cO[mt][nt][half * 2 + 1] * inv);
                *reinterpret_cast<float2*>(&hdst[(size_t)(S0 + rloc) * DHn + e]) = val;
            }
        }
    if (tid < 128) g_rowsum[(size_t)bh * Sn + S0 + tid] = rowsum[tid];
}

// ================= Kernel 3: normalize attn rows (streaming, DRAM roofline) ======
__global__ void rescale_kernel(float* __restrict__ attn) {
    int row = blockIdx.x;
    float inv = 1.f / g_rowsum[row];
    float4* p = reinterpret_cast<float4*>(attn + (size_t)row * Sn);
    int tid = threadIdx.x;
    #pragma unroll
    for (int i = 0; i < 2; i++) {
        float4 v = p[tid + i * 256];
        v.x *= inv; v.y *= inv; v.z *= inv; v.w *= inv;
        p[tid + i * 256] = v;
    }
}

// ================= Kernel 4: out = mean_h(heads) @ Wo =================
__global__ __launch_bounds__(256) void final_kernel(
    const float* __restrict__ Wo, float* __restrict__ out)
{
    __shared__ float avg[16][64];
    int r0 = blockIdx.x * 16;
    int tid = threadIdx.x;
    #pragma unroll
    for (int it = 0; it < 4; it++) {
        int i = tid + it * 256;
        int rr = i >> 6, e = i & 63;
        int R = r0 + rr;
        int bb = R >> 11, s = R & 2047;
        size_t base = ((size_t)(bb * Hn) * Sn + s) * DHn + e;
        avg[rr][e] = g_heads[base] + g_heads[base + (size_t)Sn * DHn]
                   + g_heads[base + 2 * (size_t)Sn * DHn] + g_heads[base + 3 * (size_t)Sn * DHn];
    }
    __syncthreads();
    float acc[16];
    #pragma unroll
    for (int i = 0; i < 16; i++) acc[i] = 0.f;
    int d = tid;
    #pragma unroll 16
    for (int e = 0; e < 64; e++) {
        float w = Wo[e * Dn + d];
        #pragma unroll
        for (int i = 0; i < 16; i++) acc[i] += avg[i][e] * w;
    }
    #pragma unroll
    for (int i = 0; i < 16; i++) out[(size_t)(r0 + i) * Dn + d] = acc[i];
}

// ================= launch =================
extern "C" void kernel_launch(void* const* d_in, const int* in_sizes, int n_in,
                              void* d_out, int out_size) {
    const float* q    = (const float*)d_in[0];
    const float* k    = (const float*)d_in[1];
    const float* v    = (const float*)d_in[2];
    const int*   mask = (const int*)  d_in[3];
    const float* Wq   = (const float*)d_in[4];
    const float* Wk   = (const float*)d_in[5];
    const float* Wv   = (const float*)d_in[6];
    const float* Wo   = (const float*)d_in[7];
    float* outp  = (float*)d_out;
    float* attnp = outp + (size_t)Bn * Sn * Dn;   // outputs first, attn second

    (void)in_sizes; (void)n_in; (void)out_size;

    cudaFuncSetAttribute(attn_kernel, cudaFuncAttributeMaxDynamicSharedMemorySize, 107008);

    pack_mask_kernel<<<(Bn * Sn * Sn) / 256, 256>>>(mask);
    proj_kernel<<<dim3(4, 128, 3), 256>>>(q, k, v, Wq, Wk, Wv);
    attn_kernel<<<dim3(16, 4, 8), 256, 107008>>>(attnp);
    rescale_kernel<<<Bn * Hn * Sn, 256>>>(attnp);
    final_kernel<<<(Bn * Sn) / 16, 256>>>(Wo, outp);
}

// round 10
// speedup vs baseline: 1.4393x; 1.0731x over previous
#include <cuda_runtime.h>
#include <cuda_bf16.h>

#define Bn 8
#define Sn 2048
#define Dn 256
#define Hn 4
#define DHn 64

// ---------------- scratch (static device arrays; no allocation) ----------------
__device__ float g_qs[Bn*Hn*Sn*DHn];     // 16 MB  [B,H,S,DH]  tf32-pre-rounded
__device__ float g_ks[Bn*Hn*Sn*DHn];     // 16 MB  [B,H,S,DH]  tf32-pre-rounded
__device__ float g_vs[Bn*Sn*DHn];        //  4 MB  [B,S,DH]    tf32-pre-rounded
__device__ float g_heads[Bn*Hn*Sn*DHn];  // 16 MB  [B,H,S,DH]  (carries 1/(4*rowsum))
__device__ float g_rowsum[Bn*Hn*Sn];     // 256 KB
__device__ unsigned g_mbits[Bn*Sn*(Sn/32)]; // 16.8 MB bit-packed mask

// ---------------- helpers ----------------
__device__ __forceinline__ unsigned f2tf(float x) {
    unsigned u;
    asm("cvt.rna.tf32.f32 %0, %1;" : "=r"(u) : "f"(x));
    return u;
}
__device__ __forceinline__ float tf32r(float x) { return __uint_as_float(f2tf(x)); }
__device__ __forceinline__ void mma8(float* c, const unsigned* a, const unsigned* b) {
    asm volatile("mma.sync.aligned.m16n8k8.row.col.f32.tf32.tf32.f32 "
        "{%0,%1,%2,%3}, {%4,%5,%6,%7}, {%8,%9}, {%0,%1,%2,%3};\n"
        : "+f"(c[0]), "+f"(c[1]), "+f"(c[2]), "+f"(c[3])
        : "r"(a[0]), "r"(a[1]), "r"(a[2]), "r"(a[3]), "r"(b[0]), "r"(b[1]));
}
__device__ __forceinline__ void mma16(float* c, const unsigned* a, const unsigned* b) {
    asm volatile("mma.sync.aligned.m16n8k16.row.col.f32.bf16.bf16.f32 "
        "{%0,%1,%2,%3}, {%4,%5,%6,%7}, {%8,%9}, {%0,%1,%2,%3};\n"
        : "+f"(c[0]), "+f"(c[1]), "+f"(c[2]), "+f"(c[3])
        : "r"(a[0]), "r"(a[1]), "r"(a[2]), "r"(a[3]), "r"(b[0]), "r"(b[1]));
}
__device__ __forceinline__ void bsplit(float x, __nv_bfloat16 &hi, __nv_bfloat16 &lo) {
    hi = __float2bfloat16_rn(x);
    lo = __float2bfloat16_rn(x - __bfloat162float(hi));
}

// FMA-pipe exp(s/8): magic-constant round + degree-5 poly + exponent splice. rel err ~2e-6.
__device__ __forceinline__ float fexp8(float s) {
    const float c = 0.18033688011112042f;   // log2(e)/8
    const float MAGIC = 12582912.0f;        // 1.5 * 2^23
    float t = fmaf(s, c, MAGIC);
    float k = t - MAGIC;
    float f = fmaf(s, c, -k);               // f in [-0.5, 0.5]
    float p = 1.3333558146e-3f;
    p = fmaf(p, f, 9.6181291076e-3f);
    p = fmaf(p, f, 5.5504108665e-2f);
    p = fmaf(p, f, 2.4022650696e-1f);
    p = fmaf(p, f, 6.9314718056e-1f);
    p = fmaf(p, f, 1.0f);
    int ik = __float_as_int(t) << 23;
    return __int_as_float(__float_as_int(p) + ik);
}

#define CP_ASYNC16(dst_u32, src) \
    asm volatile("cp.async.cg.shared.global [%0], [%1], 16;" :: "r"(dst_u32), "l"(src))
#define CP_ASYNC8(dst_u32, src) \
    asm volatile("cp.async.ca.shared.global [%0], [%1], 8;" :: "r"(dst_u32), "l"(src))
#define CP_COMMIT() asm volatile("cp.async.commit_group;" ::: "memory")

// ================= Kernel 0: bit-pack the mask =================
__global__ void pack_mask_kernel(const int* __restrict__ mask) {
    size_t i = (size_t)blockIdx.x * 256 + threadIdx.x;
    int m = mask[i] != 0;
    unsigned bal = __ballot_sync(0xffffffffu, m);
    if ((threadIdx.x & 31) == 0) g_mbits[i >> 5] = bal;
}

// ================= Kernel 1: projections via bf16x3 GEMM, tf32-rounded outputs ====
__global__ __launch_bounds__(256) void proj_kernel(
    const float* __restrict__ q, const float* __restrict__ k, const float* __restrict__ v,
    const float* __restrict__ Wq, const float* __restrict__ Wk, const float* __restrict__ Wv)
{
    int z = blockIdx.z;
    if (z == 2 && blockIdx.x > 0) return;
    __shared__ __nv_bfloat16 Ah[128][40];
    __shared__ __nv_bfloat16 Al[128][40];
    __shared__ __nv_bfloat16 Bh[64][40];   // stored as [n][k]
    __shared__ __nv_bfloat16 Bl[64][40];

    const float* X = (z == 0) ? q : (z == 1) ? k : v;
    const float* W = (z == 0) ? (Wq + (size_t)blockIdx.x * Dn * DHn)
                   : (z == 1) ? (Wk + (size_t)blockIdx.x * Dn * DHn) : Wv;
    int M0 = blockIdx.y * 128;
    int tid = threadIdx.x;
    int warp = tid >> 5, lane = tid & 31;
    int g = lane >> 2, t = lane & 3;
    int wm0 = (warp >> 1) * 32, wn0 = (warp & 1) * 32;

    float c[2][4][4];
    #pragma unroll
    for (int mt = 0; mt < 2; mt++)
        #pragma unroll
        for (int nt = 0; nt < 4; nt++)
            #pragma unroll
            for (int i = 0; i < 4; i++) c[mt][nt][i] = 0.f;

    for (int kc = 0; kc < 8; kc++) {
        int K0 = kc * 32;
        #pragma unroll
        for (int it = 0; it < 4; it++) {
            int i = tid + it * 256;
            int r = i >> 3, c4 = (i & 7) << 2;
            float4 val = *reinterpret_cast<const float4*>(&X[(size_t)(M0 + r) * Dn + K0 + c4]);
            __nv_bfloat16 hi, lo;
            bsplit(val.x, hi, lo); Ah[r][c4]   = hi; Al[r][c4]   = lo;
            bsplit(val.y, hi, lo); Ah[r][c4+1] = hi; Al[r][c4+1] = lo;
            bsplit(val.z, hi, lo); Ah[r][c4+2] = hi; Al[r][c4+2] = lo;
            bsplit(val.w, hi, lo); Ah[r][c4+3] = hi; Al[r][c4+3] = lo;
        }
        #pragma unroll
        for (int it = 0; it < 2; it++) {
            int i = tid + it * 256;
            int r = i >> 4, c4 = (i & 15) << 2;   // r = k row (0..31), c4 = n
            float4 val = *reinterpret_cast<const float4*>(&W[(size_t)(K0 + r) * DHn + c4]);
            __nv_bfloat16 hi, lo;
            bsplit(val.x, hi, lo); Bh[c4][r]   = hi; Bl[c4][r]   = lo;
            bsplit(val.y, hi, lo); Bh[c4+1][r] = hi; Bl[c4+1][r] = lo;
            bsplit(val.z, hi, lo); Bh[c4+2][r] = hi; Bl[c4+2][r] = lo;
            bsplit(val.w, hi, lo); Bh[c4+3][r] = hi; Bl[c4+3][r] = lo;
        }
        __syncthreads();
        #pragma unroll
        for (int kk = 0; kk < 2; kk++) {
            int k0 = kk * 16;
            unsigned ah[2][4], al[2][4], bh[4][2], bl[4][2];
            #pragma unroll
            for (int mt = 0; mt < 2; mt++) {
                int rb = wm0 + mt * 16;
                ah[mt][0] = *reinterpret_cast<const unsigned*>(&Ah[rb + g][k0 + 2*t]);
                ah[mt][1] = *reinterpret_cast<const unsigned*>(&Ah[rb + 8 + g][k0 + 2*t]);
                ah[mt][2] = *reinterpret_cast<const unsigned*>(&Ah[rb + g][k0 + 8 + 2*t]);
                ah[mt][3] = *reinterpret_cast<const unsigned*>(&Ah[rb + 8 + g][k0 + 8 + 2*t]);
                al[mt][0] = *reinterpret_cast<const unsigned*>(&Al[rb + g][k0 + 2*t]);
                al[mt][1] = *reinterpret_cast<const unsigned*>(&Al[rb + 8 + g][k0 + 2*t]);
                al[mt][2] = *reinterpret_cast<const unsigned*>(&Al[rb + g][k0 + 8 + 2*t]);
                al[mt][3] = *reinterpret_cast<const unsigned*>(&Al[rb + 8 + g][k0 + 8 + 2*t]);
            }
            #pragma unroll
            for (int nt = 0; nt < 4; nt++) {
                int cb = wn0 + nt * 8 + g;
                bh[nt][0] = *reinterpret_cast<const unsigned*>(&Bh[cb][k0 + 2*t]);
                bh[nt][1] = *reinterpret_cast<const unsigned*>(&Bh[cb][k0 + 8 + 2*t]);
                bl[nt][0] = *reinterpret_cast<const unsigned*>(&Bl[cb][k0 + 2*t]);
                bl[nt][1] = *reinterpret_cast<const unsigned*>(&Bl[cb][k0 + 8 + 2*t]);
            }
            #pragma unroll
            for (int mt = 0; mt < 2; mt++)
                #pragma unroll
                for (int nt = 0; nt < 4; nt++) {
                    mma16(c[mt][nt], ah[mt], bh[nt]);
                    mma16(c[mt][nt], ah[mt], bl[nt]);
                    mma16(c[mt][nt], al[mt], bh[nt]);
                }
        }
        __syncthreads();
    }
    #pragma unroll
    for (int mt = 0; mt < 2; mt++)
        #pragma unroll
        for (int nt = 0; nt < 4; nt++) {
            int e = wn0 + nt * 8 + 2 * t;
            #pragma unroll
            for (int half = 0; half < 2; half++) {
                int r = M0 + wm0 + mt * 16 + half * 8 + g;
                int bb = r >> 11, s = r & 2047;
                float2 val = make_float2(tf32r(c[mt][nt][half * 2]), tf32r(c[mt][nt][half * 2 + 1]));
                if (z == 2) {
                    *reinterpret_cast<float2*>(&g_vs[((size_t)bb * Sn + s) * DHn + e]) = val;
                } else {
                    float* dst = (z == 0) ? g_qs : g_ks;
                    int h = blockIdx.x;
                    *reinterpret_cast<float2*>(&dst[(((size_t)(bb * Hn + h)) * Sn + s) * DHn + e]) = val;
                }
            }
        }
}

// ================= Kernel 2: fused attention (cp.async double-buffered) ==========
// smem layout (floats):
//   Qs   [128][68]      @ 0       (8704)
//   Ks2  [2][64][68]    @ 8704    (8704)
//   Vs2  [2][64][72]    @ 17408   (9216)
//   Ps   [128][68]      @ 26624   (8704)
//   m2   [2][128][2]u32 @ 35328   (512)
//   rowsum [128]        @ 35840   (128)
// total 35968 floats = 143872 bytes
__global__ __launch_bounds__(256) void attn_kernel(float* __restrict__ attn_out)
{
    extern __shared__ float sm[];
    float* Qs = sm;                    // pitch 68
    float* Ks2 = sm + 8704;            // per-buf 4352, pitch 68
    float* Vs2 = sm + 17408;           // per-buf 4608, pitch 72
    float* Ps = sm + 26624;            // pitch 68
    unsigned* m2 = reinterpret_cast<unsigned*>(sm + 35328); // per-buf 256, pitch 2
    float* rowsum = sm + 35840;

    int st = blockIdx.x, h = blockIdx.y, b = blockIdx.z;
    int bh = b * Hn + h;
    int S0 = st * 128;
    int tid = threadIdx.x, warp = tid >> 5, lane = tid & 31;
    int g = lane >> 2, t = lane & 3;
    int wm0 = (warp >> 1) * 32, wn0 = (warp & 1) * 32;

    const float* qsrc = g_qs + ((size_t)bh * Sn + S0) * DHn;
    const float* ksrc = g_ks + (size_t)bh * Sn * DHn;
    const float* vsrc = g_vs + (size_t)b * Sn * DHn;
    const unsigned* msrc = g_mbits + ((size_t)b * Sn + S0) * (Sn / 32);
    float* aout = attn_out + (size_t)bh * Sn * Sn;

    unsigned smem_base = (unsigned)__cvta_generic_to_shared(sm);

    // async stage of K/V/mask for tile `tc` into buffer `buf`
    auto stage = [&](int tc, int buf) {
        int T0 = tc * 64;
        unsigned kbase = smem_base + (8704 + buf * 4352) * 4;
        unsigned vbase = smem_base + (17408 + buf * 4608) * 4;
        #pragma unroll
        for (int it = 0; it < 4; it++) {
            int ci = tid + it * 256;      // 1024 chunks of 16B for K
            int r = ci >> 4, c16 = ci & 15;
            CP_ASYNC16(kbase + (r * 68 + c16 * 4) * 4, &ksrc[(size_t)(T0 + r) * DHn + c16 * 4]);
            CP_ASYNC16(vbase + (r * 72 + c16 * 4) * 4, &vsrc[(size_t)(T0 + r) * DHn + c16 * 4]);
        }
        if (tid < 128) {
            unsigned mbase = smem_base + (35328 + buf * 256) * 4;
            CP_ASYNC8(mbase + tid * 8, &msrc[(size_t)tid * (Sn / 32) + (T0 >> 5)]);
        }
    };

    // prologue: kick off tile 0, stage Q with plain loads
    stage(0, 0);
    CP_COMMIT();
    #pragma unroll
    for (int it = 0; it < 8; it++) {
        int i = tid + it * 256;
        int r = i >> 4, c4 = (i & 15) << 2;
        float4 val = *reinterpret_cast<const float4*>(&qsrc[(size_t)r * DHn + c4]);
        *reinterpret_cast<float4*>(&Qs[r * 68 + c4]) = val;
    }
    if (tid < 128) rowsum[tid] = 0.f;

    float cO[2][4][4];
    #pragma unroll
    for (int mt = 0; mt < 2; mt++)
        #pragma unroll
        for (int nt = 0; nt < 4; nt++)
            #pragma unroll
            for (int i = 0; i < 4; i++) cO[mt][nt][i] = 0.f;
    float rpart[2][2] = {{0.f, 0.f}, {0.f, 0.f}};

    for (int tc = 0; tc < 32; tc++) {
        int buf = tc & 1;
        int T0 = tc * 64;
        float* Kb = Ks2 + buf * 4352;
        float* Vb = Vs2 + buf * 4608;
        unsigned* Mb = m2 + buf * 256;

        // issue next tile into the other buffer (safe: freed by last iteration's barrier)
        if (tc + 1 < 32) {
            stage(tc + 1, buf ^ 1);
            CP_COMMIT();
            asm volatile("cp.async.wait_group 1;" ::: "memory");
        } else {
            asm volatile("cp.async.wait_group 0;" ::: "memory");
        }
        __syncthreads();

        // ---- QK^T (tf32 x1) ----
        float cS[2][4][4];
        #pragma unroll
        for (int mt = 0; mt < 2; mt++)
            #pragma unroll
            for (int nt = 0; nt < 4; nt++)
                #pragma unroll
                for (int i = 0; i < 4; i++) cS[mt][nt][i] = 0.f;
        #pragma unroll
        for (int kk = 0; kk < 8; kk++) {
            int k0 = kk * 8;
            unsigned a[2][4], bf[4][2];
            #pragma unroll
            for (int mt = 0; mt < 2; mt++) {
                int rb = wm0 + mt * 16;
                a[mt][0] = __float_as_uint(Qs[(rb + g) * 68 + k0 + t]);
                a[mt][1] = __float_as_uint(Qs[(rb + 8 + g) * 68 + k0 + t]);
                a[mt][2] = __float_as_uint(Qs[(rb + g) * 68 + k0 + t + 4]);
                a[mt][3] = __float_as_uint(Qs[(rb + 8 + g) * 68 + k0 + t + 4]);
            }
            #pragma unroll
            for (int nt = 0; nt < 4; nt++) {
                int cb = wn0 + nt * 8 + g;
                bf[nt][0] = __float_as_uint(Kb[cb * 68 + k0 + t]);
                bf[nt][1] = __float_as_uint(Kb[cb * 68 + k0 + t + 4]);
            }
            #pragma unroll
            for (int mt = 0; mt < 2; mt++)
                #pragma unroll
                for (int nt = 0; nt < 4; nt++)
                    mma8(cS[mt][nt], a[mt], bf[nt]);
        }

        // ---- mask + exp (FMA pipe) + write attn + stage tf32 P ----
        #pragma unroll
        for (int mt = 0; mt < 2; mt++)
            #pragma unroll
            for (int nt = 0; nt < 4; nt++) {
                int tloc = wn0 + nt * 8 + 2 * t;
                int tg = T0 + tloc;
                #pragma unroll
                for (int half = 0; half < 2; half++) {
                    int rloc = wm0 + mt * 16 + half * 8 + g;
                    int sg = S0 + rloc;
                    unsigned mw = Mb[rloc * 2 + (tloc >> 5)];
                    int sh = tloc & 31;
                    float e0 = fexp8(cS[mt][nt][half * 2]);
                    float e1 = fexp8(cS[mt][nt][half * 2 + 1]);
                    float p0 = ((mw >> sh) & 1u)       ? e0 : 0.f;
                    float p1 = ((mw >> (sh + 1)) & 1u) ? e1 : 0.f;
                    *reinterpret_cast<float2*>(&aout[(size_t)sg * Sn + tg]) = make_float2(p0, p1);
                    *reinterpret_cast<float2*>(&Ps[rloc * 68 + tloc]) = make_float2(tf32r(p0), tf32r(p1));
                    rpart[mt][half] += p0 + p1;
                }
            }
        __syncthreads();

        // ---- heads += P @ V (tf32; raw bit loads) ----
        #pragma unroll
        for (int kk = 0; kk < 8; kk++) {
            int k0 = kk * 8;
            unsigned a[2][4], bf[4][2];
            #pragma unroll
            for (int mt = 0; mt < 2; mt++) {
                int rb = wm0 + mt * 16;
                a[mt][0] = __float_as_uint(Ps[(rb + g) * 68 + k0 + t]);
                a[mt][1] = __float_as_uint(Ps[(rb + 8 + g) * 68 + k0 + t]);
                a[mt][2] = __float_as_uint(Ps[(rb + g) * 68 + k0 + t + 4]);
                a[mt][3] = __float_as_uint(Ps[(rb + 8 + g) * 68 + k0 + t + 4]);
            }
            #pragma unroll
            for (int nt = 0; nt < 4; nt++) {
                int cb = wn0 + nt * 8 + g;
                bf[nt][0] = __float_as_uint(Vb[(k0 + t) * 72 + cb]);
                bf[nt][1] = __float_as_uint(Vb[(k0 + t + 4) * 72 + cb]);
            }
            #pragma unroll
            for (int mt = 0; mt < 2; mt++)
                #pragma unroll
                for (int nt = 0; nt < 4; nt++)
                    mma8(cO[mt][nt], a[mt], bf[nt]);
        }
        __syncthreads();   // frees Kb/Vb/Mb/Ps for next iteration's async fill / exp
    }

    // ---- rowsum reduce ----
    #pragma unroll
    for (int mt = 0; mt < 2; mt++)
        #pragma unroll
        for (int half = 0; half < 2; half++) {
            float v = rpart[mt][half];
            v += __shfl_xor_sync(0xffffffffu, v, 1);
            v += __shfl_xor_sync(0xffffffffu, v, 2);
            if (t == 0) atomicAdd(&rowsum[wm0 + mt * 16 + half * 8 + g], v);
        }
    __syncthreads();

    // ---- write heads (scaled by 0.25/rowsum) + rowsum ----
    float* hdst = g_heads + (size_t)bh * Sn * DHn;
    #pragma unroll
    for (int mt = 0; mt < 2; mt++)
        #pragma unroll
        for (int nt = 0; nt < 4; nt++) {
            int e = wn0 + nt * 8 + 2 * t;
            #pragma unroll
            for (int half = 0; half < 2; half++) {
                int rloc = wm0 + mt * 16 + half * 8 + g;
                float inv = 0.25f / rowsum[rloc];
                float2 val = make_float2(cO[mt][nt][half * 2] * inv, cO[mt][nt][half * 2 + 1] * inv);
                *reinterpret_cast<float2*>(&hdst[(size_t)(S0 + rloc) * DHn + e]) = val;
            }
        }
    if (tid < 128) g_rowsum[(size_t)bh * Sn + S0 + tid] = rowsum[tid];
}

// ================= Kernel 3: normalize attn rows (streaming, DRAM roofline) ======
__global__ void rescale_kernel(float* __restrict__ attn) {
    int row = blockIdx.x;
    float inv = 1.f / g_rowsum[row];
    float4* p = reinterpret_cast<float4*>(attn + (size_t)row * Sn);
    int tid = threadIdx.x;
    #pragma unroll
    for (int i = 0; i < 2; i++) {
        float4 v = p[tid + i * 256];
        v.x *= inv; v.y *= inv; v.z *= inv; v.w *= inv;
        p[tid + i * 256] = v;
    }
}

// ================= Kernel 4: out = mean_h(heads) @ Wo =================
__global__ __launch_bounds__(256) void final_kernel(
    const float* __restrict__ Wo, float* __restrict__ out)
{
    __shared__ float avg[16][64];
    int r0 = blockIdx.x * 16;
    int tid = threadIdx.x;
    #pragma unroll
    for (int it = 0; it < 4; it++) {
        int i = tid + it * 256;
        int rr = i >> 6, e = i & 63;
        int R = r0 + rr;
        int bb = R >> 11, s = R & 2047;
        size_t base = ((size_t)(bb * Hn) * Sn + s) * DHn + e;
        avg[rr][e] = g_heads[base] + g_heads[base + (size_t)Sn * DHn]
                   + g_heads[base + 2 * (size_t)Sn * DHn] + g_heads[base + 3 * (size_t)Sn * DHn];
    }
    __syncthreads();
    float acc[16];
    #pragma unroll
    for (int i = 0; i < 16; i++) acc[i] = 0.f;
    int d = tid;
    #pragma unroll 16
    for (int e = 0; e < 64; e++) {
        float w = Wo[e * Dn + d];
        #pragma unroll
        for (int i = 0; i < 16; i++) acc[i] += avg[i][e] * w;
    }
    #pragma unroll
    for (int i = 0; i < 16; i++) out[(size_t)(r0 + i) * Dn + d] = acc[i];
}

// ================= launch =================
extern "C" void kernel_launch(void* const* d_in, const int* in_sizes, int n_in,
                              void* d_out, int out_size) {
    const float* q    = (const float*)d_in[0];
    const float* k    = (const float*)d_in[1];
    const float* v    = (const float*)d_in[2];
    const int*   mask = (const int*)  d_in[3];
    const float* Wq   = (const float*)d_in[4];
    const float* Wk   = (const float*)d_in[5];
    const float* Wv   = (const float*)d_in[6];
    const float* Wo   = (const float*)d_in[7];
    float* outp  = (float*)d_out;
    float* attnp = outp + (size_t)Bn * Sn * Dn;   // outputs first, attn second

    (void)in_sizes; (void)n_in; (void)out_size;

    cudaFuncSetAttribute(attn_kernel, cudaFuncAttributeMaxDynamicSharedMemorySize, 143872);

    pack_mask_kernel<<<(Bn * Sn * Sn) / 256, 256>>>(mask);
    proj_kernel<<<dim3(4, 128, 3), 256>>>(q, k, v, Wq, Wk, Wv);
    attn_kernel<<<dim3(16, 4, 8), 256, 143872>>>(attnp);
    rescale_kernel<<<Bn * Hn * Sn, 256>>>(attnp);
    final_kernel<<<(Bn * Sn) / 16, 256>>>(Wo, outp);
}